// round 13
// baseline (speedup 1.0000x reference)
#include <cuda_runtime.h>
#include <cuda_bf16.h>
#include <cstdint>

#define N_NODES_MAX 50016
#define FEAT 256
#define PLANE (N_NODES_MAX * 64)

typedef unsigned long long u64t;

// ---------------- scratch ----------------
__device__ float g_xl[4 * PLANE];             // planar: plane c, [node][u]
__device__ float g_agg[N_NODES_MAX * FEAT];   // quad layout [node][u][4]
// Fragment-linear B weights for dual MMA (N=128):
// idx = ((s*4 + kc)*16 + nt)*32 + lane ; uint4 = {BhR0, BhR1, BlR0, BlR1}
__device__ uint4 g_WF[40 * 4 * 16 * 32];
// Fragment-linear B weights for final MMA (N=64):
__device__ uint4 g_WF2[40 * 4 * 8 * 32];
__device__ float g_tppA[32 * 32 * 4];
__device__ float g_tppB[32 * 32 * 4];

// ---------------- helpers ----------------
__device__ __forceinline__ u64t pack2s(float a) {
    u64t r; asm("mov.b64 %0, {%1, %1};" : "=l"(r) : "f"(a)); return r;
}
__device__ __forceinline__ void unpack2(u64t v, float& a, float& b) {
    asm("mov.b64 {%0, %1}, %2;" : "=f"(a), "=f"(b) : "l"(v));
}
__device__ __forceinline__ void ffma2(u64t& d, u64t a, u64t b) {
    asm("fma.rn.f32x2 %0, %1, %2, %0;" : "+l"(d) : "l"(a), "l"(b));
}
__device__ __forceinline__ void red_add_v4(float* p, float4 v) {
    asm volatile("red.global.add.v4.f32 [%0], {%1,%2,%3,%4};"
                 :: "l"(p), "f"(v.x), "f"(v.y), "f"(v.z), "f"(v.w) : "memory");
}
__device__ __forceinline__ void cp16(uint32_t saddr, const void* g) {
    asm volatile("cp.async.cg.shared.global [%0], [%1], 16;" :: "r"(saddr), "l"(g));
}
__device__ __forceinline__ void cp_commit() { asm volatile("cp.async.commit_group;" ::: "memory"); }
__device__ __forceinline__ void cp_waitg1() { asm volatile("cp.async.wait_group 1;" ::: "memory"); }
__device__ __forceinline__ uint32_t smem_u32(const void* p) {
    uint32_t a;
    asm("{ .reg .u64 t; cvta.to.shared.u64 t, %1; cvt.u32.u64 %0, t; }" : "=r"(a) : "l"(p));
    return a;
}
// split a pair of f32 into packed bf16x2 hi and lo parts: {lo16 = e0, hi16 = e1}
__device__ __forceinline__ void split2(float e0, float e1, uint32_t& hp, uint32_t& lp) {
    asm("cvt.rn.bf16x2.f32 %0, %1, %2;" : "=r"(hp) : "f"(e1), "f"(e0));
    float h0 = __uint_as_float(hp << 16);
    float h1 = __uint_as_float(hp & 0xFFFF0000u);
    asm("cvt.rn.bf16x2.f32 %0, %1, %2;" : "=r"(lp) : "f"(e1 - h1), "f"(e0 - h0));
}

#define MMA16816(c, a, b0, b1) \
    asm volatile("mma.sync.aligned.m16n8k16.row.col.f32.bf16.bf16.f32 " \
        "{%0,%1,%2,%3}, {%4,%5,%6,%7}, {%8,%9}, {%0,%1,%2,%3};" \
        : "+f"((c)[0]), "+f"((c)[1]), "+f"((c)[2]), "+f"((c)[3]) \
        : "r"((a)[0]), "r"((a)[1]), "r"((a)[2]), "r"((a)[3]), "r"(b0), "r"(b1))

// ---------------- prepacks ----------------
__global__ void prepack_wf_kernel(const float* __restrict__ si0, const float* __restrict__ si1,
                                  const float* __restrict__ l10, const float* __restrict__ l11) {
    int idx = blockIdx.x * blockDim.x + threadIdx.x;
    if (idx >= 40 * 4 * 16 * 32) return;
    int lane = idx & 31;
    int nt = (idx >> 5) & 15;
    int kc = (idx >> 9) & 3;
    int s = idx >> 11;
    int ch = s / 10, v = s % 10;
    int gid = lane >> 2, t2 = lane & 3;
    int n = nt * 8 + gid;
    int w = n & 63;
    const float* src = (n >= 64) ? (ch == 0 ? l10 : l11) : (ch == 0 ? si0 : si1);
    int u0 = kc * 16 + t2 * 2;
    float v00 = src[((u0 + 0) * 10 + v) * 64 + w];
    float v01 = src[((u0 + 1) * 10 + v) * 64 + w];
    float v10 = src[((u0 + 8) * 10 + v) * 64 + w];
    float v11 = src[((u0 + 9) * 10 + v) * 64 + w];
    uint32_t h0, l0, h1, l1;
    split2(v00, v01, h0, l0);
    split2(v10, v11, h1, l1);
    g_WF[idx] = make_uint4(h0, h1, l0, l1);
}

__global__ void prepack_wf2_kernel(const float* __restrict__ l20, const float* __restrict__ l21) {
    int idx = blockIdx.x * blockDim.x + threadIdx.x;
    if (idx >= 40 * 4 * 8 * 32) return;
    int lane = idx & 31;
    int nt = (idx >> 5) & 7;
    int kc = (idx >> 8) & 3;
    int s = idx >> 10;
    int ch = s / 10, v = s % 10;
    int gid = lane >> 2, t2 = lane & 3;
    int w = nt * 8 + gid;      // 0..63
    const float* src = (ch == 0) ? l20 : l21;
    int u0 = kc * 16 + t2 * 2;
    float v00 = src[((u0 + 0) * 10 + v) * 64 + w];
    float v01 = src[((u0 + 1) * 10 + v) * 64 + w];
    float v10 = src[((u0 + 8) * 10 + v) * 64 + w];
    float v11 = src[((u0 + 9) * 10 + v) * 64 + w];
    uint32_t h0, l0, h1, l1;
    split2(v00, v01, h0, l0);
    split2(v10, v11, h1, l1);
    g_WF2[idx] = make_uint4(h0, h1, l0, l1);
}

__global__ void prepack_tp_kernel(const float* __restrict__ tpw) {
    int i = blockIdx.x * blockDim.x + threadIdx.x;
    if (i >= 32 * 32) return;
    int d = i >> 5, lane = i & 31;
    const float* row = tpw + d * 256;
    float* a = g_tppA + i * 4;
    a[0] = row[lane];        a[1] = row[64 + lane];
    a[2] = row[128 + lane];  a[3] = row[192 + lane];
    float* b = g_tppB + i * 4;
    b[0] = row[32 + lane];   b[1] = row[96 + lane];
    b[2] = row[160 + lane];  b[3] = row[224 + lane];
}

__global__ void zero_agg_kernel(int n4) {
    float4* p = (float4*)g_agg;
    float4 z = make_float4(0.f, 0.f, 0.f, 0.f);
    for (int i = blockIdx.x * blockDim.x + threadIdx.x; i < n4; i += gridDim.x * blockDim.x)
        p[i] = z;
}

// ---------------- fctp dual via mma.sync (unchanged from R12) ----------------
#define OFF_XS 65536
#define OFF_ZS (65536 + 34816)
#define SMEM_NEED (65536 + 34816 + 5120)

__global__ __launch_bounds__(256, 2) void fctp_dual_mma_kernel(
    const float* __restrict__ x, const float* __restrict__ z,
    float* __restrict__ out_s, int nn)
{
    extern __shared__ char sm[];
    char* Bsm = sm;
    float* xs = (float*)(sm + OFF_XS);
    float* zs = (float*)(sm + OFF_ZS);

    const int t = threadIdx.x;
    const int wid = t >> 5;
    const int lane = t & 31;
    const int gid = lane >> 2;
    const int t2 = lane & 3;
    const int warp_m = wid & 3;
    const int warp_n = wid >> 2;
    const int nbase = blockIdx.x * 128;

    const uint32_t bsm_u = smem_u32(Bsm);

    for (int i = t; i < 1280; i += 256) {
        int node = nbase + i / 10;
        zs[i] = (node < nn) ? z[(size_t)nbase * 10 + i] : 0.f;
    }
    {
        const uint4* gsrc = g_WF;
#pragma unroll
        for (int k = 0; k < 8; k++)
            cp16(bsm_u + t * 16 + k * 4096, gsrc + t + k * 256);
        cp_commit();
    }

    float acc[2][8][4];
#pragma unroll
    for (int a = 0; a < 2; a++)
#pragma unroll
        for (int b = 0; b < 8; b++)
#pragma unroll
            for (int c = 0; c < 4; c++) acc[a][b][c] = 0.f;

    const float sc = 0.03952847075210474f;

    for (int s = 0; s < 40; s++) {
        const int ch = s / 10;
        const int v = s % 10;
        const int buf = s & 1;

        __syncthreads();

        if (v == 0) {
            for (int i = t; i < 8192; i += 256) {
                int row = i >> 6, u = i & 63;
                int node = nbase + row;
                int col = (ch == 0) ? u : (64 + 3 * u + (ch - 1));
                xs[row * 68 + u] = (node < nn) ? x[(size_t)node * 256 + col] : 0.f;
            }
        }
        if (s + 1 < 40) {
            const uint4* gsrc = g_WF + (size_t)(s + 1) * 2048;
            uint32_t dst = bsm_u + (buf ^ 1) * 32768;
#pragma unroll
            for (int k = 0; k < 8; k++)
                cp16(dst + t * 16 + k * 4096, gsrc + t + k * 256);
        }
        cp_commit();
        cp_waitg1();
        __syncthreads();

        float zr[2][2];
#pragma unroll
        for (int mt = 0; mt < 2; mt++) {
            int r = warp_m * 32 + mt * 16 + gid;
            zr[mt][0] = zs[r * 10 + v];
            zr[mt][1] = zs[(r + 8) * 10 + v];
        }

        char* Bbuf = Bsm + buf * 32768;

#pragma unroll 1
        for (int kc = 0; kc < 4; kc++) {
            uint32_t Ah[2][4], Al[2][4];
#pragma unroll
            for (int mt = 0; mt < 2; mt++) {
                int r0 = warp_m * 32 + mt * 16 + gid;
                int ub = kc * 16 + t2 * 2;
                float2 x00 = *(const float2*)(xs + r0 * 68 + ub);
                float2 x01 = *(const float2*)(xs + r0 * 68 + ub + 8);
                float2 x10 = *(const float2*)(xs + (r0 + 8) * 68 + ub);
                float2 x11 = *(const float2*)(xs + (r0 + 8) * 68 + ub + 8);
                float z0 = zr[mt][0], z1 = zr[mt][1];
                split2(x00.x * z0, x00.y * z0, Ah[mt][0], Al[mt][0]);
                split2(x10.x * z1, x10.y * z1, Ah[mt][1], Al[mt][1]);
                split2(x01.x * z0, x01.y * z0, Ah[mt][2], Al[mt][2]);
                split2(x11.x * z1, x11.y * z1, Ah[mt][3], Al[mt][3]);
            }
#pragma unroll
            for (int nt = 0; nt < 8; nt++) {
                uint4 B4 = *(const uint4*)(Bbuf + (((kc * 16) + warp_n * 8 + nt) * 32 + lane) * 16);
#pragma unroll
                for (int mt = 0; mt < 2; mt++) {
                    MMA16816(acc[mt][nt], Ah[mt], B4.x, B4.y);
                    MMA16816(acc[mt][nt], Ah[mt], B4.z, B4.w);
                    MMA16816(acc[mt][nt], Al[mt], B4.x, B4.y);
                }
            }
        }

        if (v == 9) {
#pragma unroll
            for (int mt = 0; mt < 2; mt++) {
#pragma unroll
                for (int nt = 0; nt < 8; nt++) {
                    int ntg = warp_n * 8 + nt;
                    int n0 = ntg * 8 + t2 * 2;
                    int r0 = nbase + warp_m * 32 + mt * 16 + gid;
                    int r1 = r0 + 8;
                    float c0 = acc[mt][nt][0] * sc;
                    float c1 = acc[mt][nt][1] * sc;
                    float c2 = acc[mt][nt][2] * sc;
                    float c3 = acc[mt][nt][3] * sc;
                    if (warp_n == 0) {
                        int w = n0;
                        if (ch == 0) {
                            if (r0 < nn) *(float2*)(out_s + (size_t)r0 * 256 + w) = make_float2(c0, c1);
                            if (r1 < nn) *(float2*)(out_s + (size_t)r1 * 256 + w) = make_float2(c2, c3);
                        } else {
                            int off = 64 + 3 * w + (ch - 1);
                            if (r0 < nn) {
                                out_s[(size_t)r0 * 256 + off] = c0;
                                out_s[(size_t)r0 * 256 + off + 3] = c1;
                            }
                            if (r1 < nn) {
                                out_s[(size_t)r1 * 256 + off] = c2;
                                out_s[(size_t)r1 * 256 + off + 3] = c3;
                            }
                        }
                    } else {
                        int w = n0 - 64;
                        float* xlp = g_xl + (size_t)ch * PLANE;
                        if (r0 < nn) *(float2*)(xlp + (size_t)r0 * 64 + w) = make_float2(c0, c1);
                        if (r1 < nn) *(float2*)(xlp + (size_t)r1 * 64 + w) = make_float2(c2, c3);
                    }
                    acc[mt][nt][0] = 0.f; acc[mt][nt][1] = 0.f;
                    acc[mt][nt][2] = 0.f; acc[mt][nt][3] = 0.f;
                }
            }
        }
    }
}

// ---------------- fctp final via mma.sync (N=64, unchanged from R12) ----------------
#define F_OFF_XS 32768
#define F_OFF_ZS (32768 + 34816)
#define F_SMEM_NEED (32768 + 34816 + 5120)

__global__ __launch_bounds__(256, 2) void fctp_final_mma_kernel(
    const float* __restrict__ z, float* __restrict__ out, int nn)
{
    extern __shared__ char sm[];
    char* Bsm = sm;
    float* xs = (float*)(sm + F_OFF_XS);
    float* zs = (float*)(sm + F_OFF_ZS);

    const int t = threadIdx.x;
    const int wid = t >> 5;
    const int lane = t & 31;
    const int gid = lane >> 2;
    const int t2 = lane & 3;
    const int nbase = blockIdx.x * 128;

    const uint32_t bsm_u = smem_u32(Bsm);

    for (int i = t; i < 1280; i += 256) {
        int node = nbase + i / 10;
        zs[i] = (node < nn) ? z[(size_t)nbase * 10 + i] : 0.f;
    }
    {
        const uint4* gsrc = g_WF2;
#pragma unroll
        for (int k = 0; k < 4; k++)
            cp16(bsm_u + t * 16 + k * 4096, gsrc + t + k * 256);
        cp_commit();
    }

    float acc[8][4];
#pragma unroll
    for (int b = 0; b < 8; b++)
#pragma unroll
        for (int c = 0; c < 4; c++) acc[b][c] = 0.f;

    const float sc = 0.03952847075210474f * 0.1f;
    const float4* agg4 = (const float4*)g_agg;

    for (int s = 0; s < 40; s++) {
        const int ch = s / 10;
        const int v = s % 10;
        const int buf = s & 1;

        __syncthreads();

        if (v == 0) {
            for (int i = t; i < 8192; i += 256) {
                int row = i >> 6, u = i & 63;
                int node = nbase + row;
                float val = 0.f;
                if (node < nn) {
                    float4 q = agg4[(size_t)node * 64 + u];
                    val = (ch == 0) ? q.x : (ch == 1) ? q.y : (ch == 2) ? q.z : q.w;
                }
                xs[row * 68 + u] = val;
            }
        }
        if (s + 1 < 40) {
            const uint4* gsrc = g_WF2 + (size_t)(s + 1) * 1024;
            uint32_t dst = bsm_u + (buf ^ 1) * 16384;
#pragma unroll
            for (int k = 0; k < 4; k++)
                cp16(dst + t * 16 + k * 4096, gsrc + t + k * 256);
        }
        cp_commit();
        cp_waitg1();
        __syncthreads();

        int r0g = wid * 16 + gid;
        float z0 = zs[r0g * 10 + v];
        float z1 = zs[(r0g + 8) * 10 + v];

        char* Bbuf = Bsm + buf * 16384;

#pragma unroll 1
        for (int kc = 0; kc < 4; kc++) {
            uint32_t Ah[4], Al[4];
            {
                int ub = kc * 16 + t2 * 2;
                float2 x00 = *(const float2*)(xs + r0g * 68 + ub);
                float2 x01 = *(const float2*)(xs + r0g * 68 + ub + 8);
                float2 x10 = *(const float2*)(xs + (r0g + 8) * 68 + ub);
                float2 x11 = *(const float2*)(xs + (r0g + 8) * 68 + ub + 8);
                split2(x00.x * z0, x00.y * z0, Ah[0], Al[0]);
                split2(x10.x * z1, x10.y * z1, Ah[1], Al[1]);
                split2(x01.x * z0, x01.y * z0, Ah[2], Al[2]);
                split2(x11.x * z1, x11.y * z1, Ah[3], Al[3]);
            }
#pragma unroll
            for (int nt = 0; nt < 8; nt++) {
                uint4 B4 = *(const uint4*)(Bbuf + ((kc * 8 + nt) * 32 + lane) * 16);
                MMA16816(acc[nt], Ah, B4.x, B4.y);
                MMA16816(acc[nt], Ah, B4.z, B4.w);
                MMA16816(acc[nt], Al, B4.x, B4.y);
            }
        }

        if (v == 9) {
#pragma unroll
            for (int nt = 0; nt < 8; nt++) {
                int w = nt * 8 + t2 * 2;
                int r0 = nbase + wid * 16 + gid;
                int r1 = r0 + 8;
                float c0 = acc[nt][0] * sc;
                float c1 = acc[nt][1] * sc;
                float c2 = acc[nt][2] * sc;
                float c3 = acc[nt][3] * sc;
                if (ch == 0) {
                    if (r0 < nn) {
                        float2* p = (float2*)(out + (size_t)r0 * 256 + w);
                        float2 o = *p; o.x += c0; o.y += c1; *p = o;
                    }
                    if (r1 < nn) {
                        float2* p = (float2*)(out + (size_t)r1 * 256 + w);
                        float2 o = *p; o.x += c2; o.y += c3; *p = o;
                    }
                } else {
                    int off = 64 + 3 * w + (ch - 1);
                    if (r0 < nn) {
                        out[(size_t)r0 * 256 + off] += c0;
                        out[(size_t)r0 * 256 + off + 3] += c1;
                    }
                    if (r1 < nn) {
                        out[(size_t)r1 * 256 + off] += c2;
                        out[(size_t)r1 * 256 + off + 3] += c3;
                    }
                }
                acc[nt][0] = 0.f; acc[nt][1] = 0.f;
                acc[nt][2] = 0.f; acc[nt][3] = 0.f;
            }
        }
    }
}

// ---------------- edge kernel: 8 edges/warp, 128-thread blocks ----------------
#define EPW 8
__global__ __launch_bounds__(128) void edge_kernel(
    const int* __restrict__ esrc, const int* __restrict__ edst,
    const float* __restrict__ elen, const float* __restrict__ eattr,
    int n_edges)
{
    const int warp = threadIdx.x >> 5;
    const int lane = threadIdx.x & 31;
    const int ebase = (blockIdx.x * 4 + warp) * EPW;
    if (ebase >= n_edges) return;

    float el[EPW];
    int esafe[EPW];
    bool valid[EPW];
#pragma unroll
    for (int j = 0; j < EPW; j++) {
        int e = ebase + j;
        valid[j] = (e < n_edges);
        esafe[j] = valid[j] ? e : (n_edges - 1);
        el[j] = elen[(size_t)esafe[j] * 32 + lane];
    }

    u64t acc2[EPW * 4];
#pragma unroll
    for (int i = 0; i < EPW * 4; i++) acc2[i] = 0ull;
    const ulonglong2* tpA8 = (const ulonglong2*)g_tppA;
    const ulonglong2* tpB8 = (const ulonglong2*)g_tppB;
#pragma unroll 4
    for (int d = 0; d < 32; d++) {
        ulonglong2 tA = tpA8[d * 32 + lane];
        ulonglong2 tB = tpB8[d * 32 + lane];
#pragma unroll
        for (int j = 0; j < EPW; j++) {
            u64t ed = pack2s(__shfl_sync(0xffffffffu, el[j], d));
            ffma2(acc2[j * 4 + 0], ed, tA.x);
            ffma2(acc2[j * 4 + 1], ed, tA.y);
            ffma2(acc2[j * 4 + 2], ed, tB.x);
            ffma2(acc2[j * 4 + 3], ed, tB.y);
        }
    }

    const float ISQ2 = 0.7071067811865476f;
    const float ISQ3 = 0.5773502691896258f;

#pragma unroll
    for (int j = 0; j < EPW; j++) {
        if (!valid[j]) continue;
        int e = esafe[j];
        int src = esrc[e];
        int dst = edst[e];
        float4 at = ((const float4*)eattr)[e];

        float wv[8];
        unpack2(acc2[j * 4 + 0], wv[0], wv[1]);
        unpack2(acc2[j * 4 + 1], wv[2], wv[3]);
        unpack2(acc2[j * 4 + 2], wv[4], wv[5]);
        unpack2(acc2[j * 4 + 3], wv[6], wv[7]);

        const float* xb = g_xl + (size_t)src * 64;
        float* aggp = g_agg + (size_t)dst * FEAT;
#pragma unroll
        for (int h = 0; h < 2; h++) {
            int u = lane + 32 * h;
            float x0  = xb[u];
            float x10 = xb[1 * PLANE + u];
            float x11 = xb[2 * PLANE + u];
            float x12 = xb[3 * PLANE + u];
            float w1  = wv[h * 4 + 0];
            float w2v = wv[h * 4 + 1];
            float w3  = wv[h * 4 + 2];
            float w4v = wv[h * 4 + 3];
            float dot = x10 * at.y + x11 * at.z + x12 * at.w;
            float4 o;
            o.x = ISQ2 * (w1 * x0 * at.x + ISQ3 * w4v * dot);
            o.y = ISQ2 * (w2v * x0 * at.y + w3 * x10 * at.x);
            o.z = ISQ2 * (w2v * x0 * at.z + w3 * x11 * at.x);
            o.w = ISQ2 * (w2v * x0 * at.w + w3 * x12 * at.x);
            red_add_v4(aggp + u * 4, o);
        }
    }
}

// ---------------- launch ----------------
extern "C" void kernel_launch(void* const* d_in, const int* in_sizes, int n_in,
                              void* d_out, int out_size) {
    const float* x     = (const float*)d_in[0];
    const float* z     = (const float*)d_in[1];
    const int*   esrc  = (const int*)d_in[2];
    const int*   edst  = (const int*)d_in[3];
    const float* elen  = (const float*)d_in[4];
    const float* eattr = (const float*)d_in[5];
    const float* Wsi0  = (const float*)d_in[6];
    const float* Wsi1  = (const float*)d_in[7];
    const float* Wl10  = (const float*)d_in[8];
    const float* Wl11  = (const float*)d_in[9];
    const float* Wl20  = (const float*)d_in[10];
    const float* Wl21  = (const float*)d_in[11];
    const float* tpw   = (const float*)d_in[12];
    float* out = (float*)d_out;

    const int n_nodes = in_sizes[0] / FEAT;
    const int n_edges = in_sizes[2];

    cudaFuncSetAttribute(fctp_dual_mma_kernel,
                         cudaFuncAttributeMaxDynamicSharedMemorySize, SMEM_NEED);
    cudaFuncSetAttribute(fctp_final_mma_kernel,
                         cudaFuncAttributeMaxDynamicSharedMemorySize, F_SMEM_NEED);

    prepack_wf_kernel<<<(40 * 4 * 16 * 32 + 255) / 256, 256>>>(Wsi0, Wsi1, Wl10, Wl11);
    prepack_wf2_kernel<<<(40 * 4 * 8 * 32 + 255) / 256, 256>>>(Wl20, Wl21);
    prepack_tp_kernel<<<4, 256>>>(tpw);
    zero_agg_kernel<<<512, 256>>>(n_nodes * (FEAT / 4));

    const int ntiles = (n_nodes + 127) / 128;
    fctp_dual_mma_kernel<<<ntiles, 256, SMEM_NEED>>>(x, z, out, n_nodes);

    const int edges_per_block = 4 * EPW;
    edge_kernel<<<(n_edges + edges_per_block - 1) / edges_per_block, 128>>>(
        esrc, edst, elen, eattr, n_edges);

    fctp_final_mma_kernel<<<ntiles, 256, F_SMEM_NEED>>>(z, out, n_nodes);
}

// round 14
// speedup vs baseline: 1.1162x; 1.1162x over previous
#include <cuda_runtime.h>
#include <cuda_bf16.h>
#include <cstdint>

#define N_NODES_MAX 50016
#define FEAT 256
#define PLANE (N_NODES_MAX * 64)

typedef unsigned long long u64t;

// ---------------- scratch ----------------
__device__ float g_xl[4 * PLANE];             // planar: plane c, [node][u]
__device__ float g_agg[N_NODES_MAX * FEAT];   // quad layout [node][u][4]
// Fragment-linear B weights for dual MMA (N=128):
// idx = ((s*4 + kc)*16 + nt)*32 + lane ; uint4 = {BhR0, BhR1, BlR0, BlR1}
__device__ uint4 g_WF[40 * 4 * 16 * 32];
// Fragment-linear B weights for final MMA (N=64):
__device__ uint4 g_WF2[40 * 4 * 8 * 32];
__device__ float g_tppA[32 * 32 * 4];
__device__ float g_tppB[32 * 32 * 4];

// ---------------- helpers ----------------
__device__ __forceinline__ u64t pack2s(float a) {
    u64t r; asm("mov.b64 %0, {%1, %1};" : "=l"(r) : "f"(a)); return r;
}
__device__ __forceinline__ void unpack2(u64t v, float& a, float& b) {
    asm("mov.b64 {%0, %1}, %2;" : "=f"(a), "=f"(b) : "l"(v));
}
__device__ __forceinline__ void ffma2(u64t& d, u64t a, u64t b) {
    asm("fma.rn.f32x2 %0, %1, %2, %0;" : "+l"(d) : "l"(a), "l"(b));
}
__device__ __forceinline__ void red_add_v4(float* p, float4 v) {
    asm volatile("red.global.add.v4.f32 [%0], {%1,%2,%3,%4};"
                 :: "l"(p), "f"(v.x), "f"(v.y), "f"(v.z), "f"(v.w) : "memory");
}
__device__ __forceinline__ void cp16(uint32_t saddr, const void* g) {
    asm volatile("cp.async.cg.shared.global [%0], [%1], 16;" :: "r"(saddr), "l"(g));
}
__device__ __forceinline__ void cp_commit() { asm volatile("cp.async.commit_group;" ::: "memory"); }
__device__ __forceinline__ void cp_waitg1() { asm volatile("cp.async.wait_group 1;" ::: "memory"); }
__device__ __forceinline__ uint32_t smem_u32(const void* p) {
    uint32_t a;
    asm("{ .reg .u64 t; cvta.to.shared.u64 t, %1; cvt.u32.u64 %0, t; }" : "=r"(a) : "l"(p));
    return a;
}
// split a pair of f32 into packed bf16x2 hi and lo parts: {lo16 = e0, hi16 = e1}
__device__ __forceinline__ void split2(float e0, float e1, uint32_t& hp, uint32_t& lp) {
    asm("cvt.rn.bf16x2.f32 %0, %1, %2;" : "=r"(hp) : "f"(e1), "f"(e0));
    float h0 = __uint_as_float(hp << 16);
    float h1 = __uint_as_float(hp & 0xFFFF0000u);
    asm("cvt.rn.bf16x2.f32 %0, %1, %2;" : "=r"(lp) : "f"(e1 - h1), "f"(e0 - h0));
}

#define MMA16816(c, a, b0, b1) \
    asm volatile("mma.sync.aligned.m16n8k16.row.col.f32.bf16.bf16.f32 " \
        "{%0,%1,%2,%3}, {%4,%5,%6,%7}, {%8,%9}, {%0,%1,%2,%3};" \
        : "+f"((c)[0]), "+f"((c)[1]), "+f"((c)[2]), "+f"((c)[3]) \
        : "r"((a)[0]), "r"((a)[1]), "r"((a)[2]), "r"((a)[3]), "r"(b0), "r"(b1))

// ---------------- prepacks ----------------
__global__ void prepack_wf_kernel(const float* __restrict__ si0, const float* __restrict__ si1,
                                  const float* __restrict__ l10, const float* __restrict__ l11) {
    int idx = blockIdx.x * blockDim.x + threadIdx.x;
    if (idx >= 40 * 4 * 16 * 32) return;
    int lane = idx & 31;
    int nt = (idx >> 5) & 15;
    int kc = (idx >> 9) & 3;
    int s = idx >> 11;
    int ch = s / 10, v = s % 10;
    int gid = lane >> 2, t2 = lane & 3;
    int n = nt * 8 + gid;
    int w = n & 63;
    const float* src = (n >= 64) ? (ch == 0 ? l10 : l11) : (ch == 0 ? si0 : si1);
    int u0 = kc * 16 + t2 * 2;
    float v00 = src[((u0 + 0) * 10 + v) * 64 + w];
    float v01 = src[((u0 + 1) * 10 + v) * 64 + w];
    float v10 = src[((u0 + 8) * 10 + v) * 64 + w];
    float v11 = src[((u0 + 9) * 10 + v) * 64 + w];
    uint32_t h0, l0, h1, l1;
    split2(v00, v01, h0, l0);
    split2(v10, v11, h1, l1);
    g_WF[idx] = make_uint4(h0, h1, l0, l1);
}

__global__ void prepack_wf2_kernel(const float* __restrict__ l20, const float* __restrict__ l21) {
    int idx = blockIdx.x * blockDim.x + threadIdx.x;
    if (idx >= 40 * 4 * 8 * 32) return;
    int lane = idx & 31;
    int nt = (idx >> 5) & 7;
    int kc = (idx >> 8) & 3;
    int s = idx >> 10;
    int ch = s / 10, v = s % 10;
    int gid = lane >> 2, t2 = lane & 3;
    int w = nt * 8 + gid;      // 0..63
    const float* src = (ch == 0) ? l20 : l21;
    int u0 = kc * 16 + t2 * 2;
    float v00 = src[((u0 + 0) * 10 + v) * 64 + w];
    float v01 = src[((u0 + 1) * 10 + v) * 64 + w];
    float v10 = src[((u0 + 8) * 10 + v) * 64 + w];
    float v11 = src[((u0 + 9) * 10 + v) * 64 + w];
    uint32_t h0, l0, h1, l1;
    split2(v00, v01, h0, l0);
    split2(v10, v11, h1, l1);
    g_WF2[idx] = make_uint4(h0, h1, l0, l1);
}

__global__ void prepack_tp_kernel(const float* __restrict__ tpw) {
    int i = blockIdx.x * blockDim.x + threadIdx.x;
    if (i >= 32 * 32) return;
    int d = i >> 5, lane = i & 31;
    const float* row = tpw + d * 256;
    float* a = g_tppA + i * 4;
    a[0] = row[lane];        a[1] = row[64 + lane];
    a[2] = row[128 + lane];  a[3] = row[192 + lane];
    float* b = g_tppB + i * 4;
    b[0] = row[32 + lane];   b[1] = row[96 + lane];
    b[2] = row[160 + lane];  b[3] = row[224 + lane];
}

__global__ void zero_agg_kernel(int n4) {
    float4* p = (float4*)g_agg;
    float4 z = make_float4(0.f, 0.f, 0.f, 0.f);
    for (int i = blockIdx.x * blockDim.x + threadIdx.x; i < n4; i += gridDim.x * blockDim.x)
        p[i] = z;
}

// ---------------- fctp dual via mma.sync (unchanged from R12) ----------------
#define OFF_XS 65536
#define OFF_ZS (65536 + 34816)
#define SMEM_NEED (65536 + 34816 + 5120)

__global__ __launch_bounds__(256, 2) void fctp_dual_mma_kernel(
    const float* __restrict__ x, const float* __restrict__ z,
    float* __restrict__ out_s, int nn)
{
    extern __shared__ char sm[];
    char* Bsm = sm;
    float* xs = (float*)(sm + OFF_XS);
    float* zs = (float*)(sm + OFF_ZS);

    const int t = threadIdx.x;
    const int wid = t >> 5;
    const int lane = t & 31;
    const int gid = lane >> 2;
    const int t2 = lane & 3;
    const int warp_m = wid & 3;
    const int warp_n = wid >> 2;
    const int nbase = blockIdx.x * 128;

    const uint32_t bsm_u = smem_u32(Bsm);

    for (int i = t; i < 1280; i += 256) {
        int node = nbase + i / 10;
        zs[i] = (node < nn) ? z[(size_t)nbase * 10 + i] : 0.f;
    }
    {
        const uint4* gsrc = g_WF;
#pragma unroll
        for (int k = 0; k < 8; k++)
            cp16(bsm_u + t * 16 + k * 4096, gsrc + t + k * 256);
        cp_commit();
    }

    float acc[2][8][4];
#pragma unroll
    for (int a = 0; a < 2; a++)
#pragma unroll
        for (int b = 0; b < 8; b++)
#pragma unroll
            for (int c = 0; c < 4; c++) acc[a][b][c] = 0.f;

    const float sc = 0.03952847075210474f;

    for (int s = 0; s < 40; s++) {
        const int ch = s / 10;
        const int v = s % 10;
        const int buf = s & 1;

        __syncthreads();

        if (v == 0) {
            for (int i = t; i < 8192; i += 256) {
                int row = i >> 6, u = i & 63;
                int node = nbase + row;
                int col = (ch == 0) ? u : (64 + 3 * u + (ch - 1));
                xs[row * 68 + u] = (node < nn) ? x[(size_t)node * 256 + col] : 0.f;
            }
        }
        if (s + 1 < 40) {
            const uint4* gsrc = g_WF + (size_t)(s + 1) * 2048;
            uint32_t dst = bsm_u + (buf ^ 1) * 32768;
#pragma unroll
            for (int k = 0; k < 8; k++)
                cp16(dst + t * 16 + k * 4096, gsrc + t + k * 256);
        }
        cp_commit();
        cp_waitg1();
        __syncthreads();

        float zr[2][2];
#pragma unroll
        for (int mt = 0; mt < 2; mt++) {
            int r = warp_m * 32 + mt * 16 + gid;
            zr[mt][0] = zs[r * 10 + v];
            zr[mt][1] = zs[(r + 8) * 10 + v];
        }

        char* Bbuf = Bsm + buf * 32768;

#pragma unroll 1
        for (int kc = 0; kc < 4; kc++) {
            uint32_t Ah[2][4], Al[2][4];
#pragma unroll
            for (int mt = 0; mt < 2; mt++) {
                int r0 = warp_m * 32 + mt * 16 + gid;
                int ub = kc * 16 + t2 * 2;
                float2 x00 = *(const float2*)(xs + r0 * 68 + ub);
                float2 x01 = *(const float2*)(xs + r0 * 68 + ub + 8);
                float2 x10 = *(const float2*)(xs + (r0 + 8) * 68 + ub);
                float2 x11 = *(const float2*)(xs + (r0 + 8) * 68 + ub + 8);
                float z0 = zr[mt][0], z1 = zr[mt][1];
                split2(x00.x * z0, x00.y * z0, Ah[mt][0], Al[mt][0]);
                split2(x10.x * z1, x10.y * z1, Ah[mt][1], Al[mt][1]);
                split2(x01.x * z0, x01.y * z0, Ah[mt][2], Al[mt][2]);
                split2(x11.x * z1, x11.y * z1, Ah[mt][3], Al[mt][3]);
            }
#pragma unroll
            for (int nt = 0; nt < 8; nt++) {
                uint4 B4 = *(const uint4*)(Bbuf + (((kc * 16) + warp_n * 8 + nt) * 32 + lane) * 16);
#pragma unroll
                for (int mt = 0; mt < 2; mt++) {
                    MMA16816(acc[mt][nt], Ah[mt], B4.x, B4.y);
                    MMA16816(acc[mt][nt], Ah[mt], B4.z, B4.w);
                    MMA16816(acc[mt][nt], Al[mt], B4.x, B4.y);
                }
            }
        }

        if (v == 9) {
#pragma unroll
            for (int mt = 0; mt < 2; mt++) {
#pragma unroll
                for (int nt = 0; nt < 8; nt++) {
                    int ntg = warp_n * 8 + nt;
                    int n0 = ntg * 8 + t2 * 2;
                    int r0 = nbase + warp_m * 32 + mt * 16 + gid;
                    int r1 = r0 + 8;
                    float c0 = acc[mt][nt][0] * sc;
                    float c1 = acc[mt][nt][1] * sc;
                    float c2 = acc[mt][nt][2] * sc;
                    float c3 = acc[mt][nt][3] * sc;
                    if (warp_n == 0) {
                        int w = n0;
                        if (ch == 0) {
                            if (r0 < nn) *(float2*)(out_s + (size_t)r0 * 256 + w) = make_float2(c0, c1);
                            if (r1 < nn) *(float2*)(out_s + (size_t)r1 * 256 + w) = make_float2(c2, c3);
                        } else {
                            int off = 64 + 3 * w + (ch - 1);
                            if (r0 < nn) {
                                out_s[(size_t)r0 * 256 + off] = c0;
                                out_s[(size_t)r0 * 256 + off + 3] = c1;
                            }
                            if (r1 < nn) {
                                out_s[(size_t)r1 * 256 + off] = c2;
                                out_s[(size_t)r1 * 256 + off + 3] = c3;
                            }
                        }
                    } else {
                        int w = n0 - 64;
                        float* xlp = g_xl + (size_t)ch * PLANE;
                        if (r0 < nn) *(float2*)(xlp + (size_t)r0 * 64 + w) = make_float2(c0, c1);
                        if (r1 < nn) *(float2*)(xlp + (size_t)r1 * 64 + w) = make_float2(c2, c3);
                    }
                    acc[mt][nt][0] = 0.f; acc[mt][nt][1] = 0.f;
                    acc[mt][nt][2] = 0.f; acc[mt][nt][3] = 0.f;
                }
            }
        }
    }
}

// ---------------- fctp final via mma.sync (N=64, unchanged from R12) ----------------
#define F_OFF_XS 32768
#define F_OFF_ZS (32768 + 34816)
#define F_SMEM_NEED (32768 + 34816 + 5120)

__global__ __launch_bounds__(256, 2) void fctp_final_mma_kernel(
    const float* __restrict__ z, float* __restrict__ out, int nn)
{
    extern __shared__ char sm[];
    char* Bsm = sm;
    float* xs = (float*)(sm + F_OFF_XS);
    float* zs = (float*)(sm + F_OFF_ZS);

    const int t = threadIdx.x;
    const int wid = t >> 5;
    const int lane = t & 31;
    const int gid = lane >> 2;
    const int t2 = lane & 3;
    const int nbase = blockIdx.x * 128;

    const uint32_t bsm_u = smem_u32(Bsm);

    for (int i = t; i < 1280; i += 256) {
        int node = nbase + i / 10;
        zs[i] = (node < nn) ? z[(size_t)nbase * 10 + i] : 0.f;
    }
    {
        const uint4* gsrc = g_WF2;
#pragma unroll
        for (int k = 0; k < 4; k++)
            cp16(bsm_u + t * 16 + k * 4096, gsrc + t + k * 256);
        cp_commit();
    }

    float acc[8][4];
#pragma unroll
    for (int b = 0; b < 8; b++)
#pragma unroll
        for (int c = 0; c < 4; c++) acc[b][c] = 0.f;

    const float sc = 0.03952847075210474f * 0.1f;
    const float4* agg4 = (const float4*)g_agg;

    for (int s = 0; s < 40; s++) {
        const int ch = s / 10;
        const int v = s % 10;
        const int buf = s & 1;

        __syncthreads();

        if (v == 0) {
            for (int i = t; i < 8192; i += 256) {
                int row = i >> 6, u = i & 63;
                int node = nbase + row;
                float val = 0.f;
                if (node < nn) {
                    float4 q = agg4[(size_t)node * 64 + u];
                    val = (ch == 0) ? q.x : (ch == 1) ? q.y : (ch == 2) ? q.z : q.w;
                }
                xs[row * 68 + u] = val;
            }
        }
        if (s + 1 < 40) {
            const uint4* gsrc = g_WF2 + (size_t)(s + 1) * 1024;
            uint32_t dst = bsm_u + (buf ^ 1) * 16384;
#pragma unroll
            for (int k = 0; k < 4; k++)
                cp16(dst + t * 16 + k * 4096, gsrc + t + k * 256);
        }
        cp_commit();
        cp_waitg1();
        __syncthreads();

        int r0g = wid * 16 + gid;
        float z0 = zs[r0g * 10 + v];
        float z1 = zs[(r0g + 8) * 10 + v];

        char* Bbuf = Bsm + buf * 16384;

#pragma unroll 1
        for (int kc = 0; kc < 4; kc++) {
            uint32_t Ah[4], Al[4];
            {
                int ub = kc * 16 + t2 * 2;
                float2 x00 = *(const float2*)(xs + r0g * 68 + ub);
                float2 x01 = *(const float2*)(xs + r0g * 68 + ub + 8);
                float2 x10 = *(const float2*)(xs + (r0g + 8) * 68 + ub);
                float2 x11 = *(const float2*)(xs + (r0g + 8) * 68 + ub + 8);
                split2(x00.x * z0, x00.y * z0, Ah[0], Al[0]);
                split2(x10.x * z1, x10.y * z1, Ah[1], Al[1]);
                split2(x01.x * z0, x01.y * z0, Ah[2], Al[2]);
                split2(x11.x * z1, x11.y * z1, Ah[3], Al[3]);
            }
#pragma unroll
            for (int nt = 0; nt < 8; nt++) {
                uint4 B4 = *(const uint4*)(Bbuf + ((kc * 8 + nt) * 32 + lane) * 16);
                MMA16816(acc[nt], Ah, B4.x, B4.y);
                MMA16816(acc[nt], Ah, B4.z, B4.w);
                MMA16816(acc[nt], Al, B4.x, B4.y);
            }
        }

        if (v == 9) {
#pragma unroll
            for (int nt = 0; nt < 8; nt++) {
                int w = nt * 8 + t2 * 2;
                int r0 = nbase + wid * 16 + gid;
                int r1 = r0 + 8;
                float c0 = acc[nt][0] * sc;
                float c1 = acc[nt][1] * sc;
                float c2 = acc[nt][2] * sc;
                float c3 = acc[nt][3] * sc;
                if (ch == 0) {
                    if (r0 < nn) {
                        float2* p = (float2*)(out + (size_t)r0 * 256 + w);
                        float2 o = *p; o.x += c0; o.y += c1; *p = o;
                    }
                    if (r1 < nn) {
                        float2* p = (float2*)(out + (size_t)r1 * 256 + w);
                        float2 o = *p; o.x += c2; o.y += c3; *p = o;
                    }
                } else {
                    int off = 64 + 3 * w + (ch - 1);
                    if (r0 < nn) {
                        out[(size_t)r0 * 256 + off] += c0;
                        out[(size_t)r0 * 256 + off + 3] += c1;
                    }
                    if (r1 < nn) {
                        out[(size_t)r1 * 256 + off] += c2;
                        out[(size_t)r1 * 256 + off + 3] += c3;
                    }
                }
                acc[nt][0] = 0.f; acc[nt][1] = 0.f;
                acc[nt][2] = 0.f; acc[nt][3] = 0.f;
            }
        }
    }
}

// ---------------- edge kernel: 4 edges/warp, gathers issued before GEMM ----------------
#define EPW 4
__global__ __launch_bounds__(256) void edge_kernel(
    const int* __restrict__ esrc, const int* __restrict__ edst,
    const float* __restrict__ elen, const float* __restrict__ eattr,
    int n_edges)
{
    const int warp = threadIdx.x >> 5;
    const int lane = threadIdx.x & 31;
    const int ebase = (blockIdx.x * 8 + warp) * EPW;
    if (ebase >= n_edges) return;

    float el[EPW];
    int esafe[EPW];
    bool valid[EPW];
#pragma unroll
    for (int j = 0; j < EPW; j++) {
        int e = ebase + j;
        valid[j] = (e < n_edges);
        esafe[j] = valid[j] ? e : (n_edges - 1);
        el[j] = elen[(size_t)esafe[j] * 32 + lane];
    }

    // Issue ALL gathers before the GEMM so their latency is covered by compute.
    float gx[EPW][8];
#pragma unroll
    for (int j = 0; j < EPW; j++) {
        const float* xb = g_xl + (size_t)esrc[esafe[j]] * 64;
#pragma unroll
        for (int h = 0; h < 2; h++) {
            int u = lane + 32 * h;
            gx[j][h * 4 + 0] = xb[u];
            gx[j][h * 4 + 1] = xb[1 * PLANE + u];
            gx[j][h * 4 + 2] = xb[2 * PLANE + u];
            gx[j][h * 4 + 3] = xb[3 * PLANE + u];
        }
    }

    // per-edge weight GEMM, lane-exact columns, packed f32x2
    u64t acc2[EPW * 4];
#pragma unroll
    for (int i = 0; i < EPW * 4; i++) acc2[i] = 0ull;
    const ulonglong2* tpA8 = (const ulonglong2*)g_tppA;
    const ulonglong2* tpB8 = (const ulonglong2*)g_tppB;
#pragma unroll 8
    for (int d = 0; d < 32; d++) {
        ulonglong2 tA = tpA8[d * 32 + lane];
        ulonglong2 tB = tpB8[d * 32 + lane];
#pragma unroll
        for (int j = 0; j < EPW; j++) {
            u64t ed = pack2s(__shfl_sync(0xffffffffu, el[j], d));
            ffma2(acc2[j * 4 + 0], ed, tA.x);
            ffma2(acc2[j * 4 + 1], ed, tA.y);
            ffma2(acc2[j * 4 + 2], ed, tB.x);
            ffma2(acc2[j * 4 + 3], ed, tB.y);
        }
    }

    const float ISQ2 = 0.7071067811865476f;
    const float ISQ3 = 0.5773502691896258f;

#pragma unroll
    for (int j = 0; j < EPW; j++) {
        if (!valid[j]) continue;
        int e = esafe[j];
        int dst = edst[e];
        float4 at = ((const float4*)eattr)[e];

        float wv[8];
        unpack2(acc2[j * 4 + 0], wv[0], wv[1]);
        unpack2(acc2[j * 4 + 1], wv[2], wv[3]);
        unpack2(acc2[j * 4 + 2], wv[4], wv[5]);
        unpack2(acc2[j * 4 + 3], wv[6], wv[7]);

        float* aggp = g_agg + (size_t)dst * FEAT;
#pragma unroll
        for (int h = 0; h < 2; h++) {
            int u = lane + 32 * h;
            float x0  = gx[j][h * 4 + 0];
            float x10 = gx[j][h * 4 + 1];
            float x11 = gx[j][h * 4 + 2];
            float x12 = gx[j][h * 4 + 3];
            float w1  = wv[h * 4 + 0];
            float w2v = wv[h * 4 + 1];
            float w3  = wv[h * 4 + 2];
            float w4v = wv[h * 4 + 3];
            float dot = x10 * at.y + x11 * at.z + x12 * at.w;
            float4 o;
            o.x = ISQ2 * (w1 * x0 * at.x + ISQ3 * w4v * dot);
            o.y = ISQ2 * (w2v * x0 * at.y + w3 * x10 * at.x);
            o.z = ISQ2 * (w2v * x0 * at.z + w3 * x11 * at.x);
            o.w = ISQ2 * (w2v * x0 * at.w + w3 * x12 * at.x);
            red_add_v4(aggp + u * 4, o);
        }
    }
}

// ---------------- launch ----------------
extern "C" void kernel_launch(void* const* d_in, const int* in_sizes, int n_in,
                              void* d_out, int out_size) {
    const float* x     = (const float*)d_in[0];
    const float* z     = (const float*)d_in[1];
    const int*   esrc  = (const int*)d_in[2];
    const int*   edst  = (const int*)d_in[3];
    const float* elen  = (const float*)d_in[4];
    const float* eattr = (const float*)d_in[5];
    const float* Wsi0  = (const float*)d_in[6];
    const float* Wsi1  = (const float*)d_in[7];
    const float* Wl10  = (const float*)d_in[8];
    const float* Wl11  = (const float*)d_in[9];
    const float* Wl20  = (const float*)d_in[10];
    const float* Wl21  = (const float*)d_in[11];
    const float* tpw   = (const float*)d_in[12];
    float* out = (float*)d_out;

    const int n_nodes = in_sizes[0] / FEAT;
    const int n_edges = in_sizes[2];

    cudaFuncSetAttribute(fctp_dual_mma_kernel,
                         cudaFuncAttributeMaxDynamicSharedMemorySize, SMEM_NEED);
    cudaFuncSetAttribute(fctp_final_mma_kernel,
                         cudaFuncAttributeMaxDynamicSharedMemorySize, F_SMEM_NEED);

    prepack_wf_kernel<<<(40 * 4 * 16 * 32 + 255) / 256, 256>>>(Wsi0, Wsi1, Wl10, Wl11);
    prepack_wf2_kernel<<<(40 * 4 * 8 * 32 + 255) / 256, 256>>>(Wl20, Wl21);
    prepack_tp_kernel<<<4, 256>>>(tpw);
    zero_agg_kernel<<<512, 256>>>(n_nodes * (FEAT / 4));

    const int ntiles = (n_nodes + 127) / 128;
    fctp_dual_mma_kernel<<<ntiles, 256, SMEM_NEED>>>(x, z, out, n_nodes);

    const int edges_per_block = 8 * EPW;
    edge_kernel<<<(n_edges + edges_per_block - 1) / edges_per_block, 256>>>(
        esrc, edst, elen, eattr, n_edges);

    fctp_final_mma_kernel<<<ntiles, 256, F_SMEM_NEED>>>(z, out, n_nodes);
}

// round 15
// speedup vs baseline: 1.2835x; 1.1499x over previous
#include <cuda_runtime.h>
#include <cuda_bf16.h>
#include <cstdint>

#define N_NODES_MAX 50016
#define FEAT 256
#define PLANE (N_NODES_MAX * 64)

typedef unsigned long long u64t;

// ---------------- scratch ----------------
__device__ float g_xl[4 * PLANE];             // planar: plane c, [node][u]
__device__ float g_agg[N_NODES_MAX * FEAT];   // quad layout [node][u][4]
// Fragment-linear tf32 B weights for dual MMA (N=128):
// idx = ((s*4 + kc)*16 + nt)*32 + lane ; uint4 = tf32 {b0c0, b1c0, b0c1, b1c1}
__device__ uint4 g_WF[40 * 4 * 16 * 32];
// Fragment-linear tf32 B weights for final MMA (N=64):
__device__ uint4 g_WF2[40 * 4 * 8 * 32];
__device__ float g_tppA[32 * 32 * 4];
__device__ float g_tppB[32 * 32 * 4];

// ---------------- helpers ----------------
__device__ __forceinline__ u64t pack2s(float a) {
    u64t r; asm("mov.b64 %0, {%1, %1};" : "=l"(r) : "f"(a)); return r;
}
__device__ __forceinline__ void unpack2(u64t v, float& a, float& b) {
    asm("mov.b64 {%0, %1}, %2;" : "=f"(a), "=f"(b) : "l"(v));
}
__device__ __forceinline__ void ffma2(u64t& d, u64t a, u64t b) {
    asm("fma.rn.f32x2 %0, %1, %2, %0;" : "+l"(d) : "l"(a), "l"(b));
}
__device__ __forceinline__ void red_add_v4(float* p, float4 v) {
    asm volatile("red.global.add.v4.f32 [%0], {%1,%2,%3,%4};"
                 :: "l"(p), "f"(v.x), "f"(v.y), "f"(v.z), "f"(v.w) : "memory");
}
__device__ __forceinline__ void cp16(uint32_t saddr, const void* g) {
    asm volatile("cp.async.cg.shared.global [%0], [%1], 16;" :: "r"(saddr), "l"(g));
}
__device__ __forceinline__ void cp_commit() { asm volatile("cp.async.commit_group;" ::: "memory"); }
__device__ __forceinline__ void cp_waitg1() { asm volatile("cp.async.wait_group 1;" ::: "memory"); }
__device__ __forceinline__ uint32_t smem_u32(const void* p) {
    uint32_t a;
    asm("{ .reg .u64 t; cvta.to.shared.u64 t, %1; cvt.u32.u64 %0, t; }" : "=r"(a) : "l"(p));
    return a;
}
__device__ __forceinline__ uint32_t tf32c(float f) {
    uint32_t r; asm("cvt.rna.tf32.f32 %0, %1;" : "=r"(r) : "f"(f)); return r;
}

#define MMATF32(c, a0, a1, a2, a3, b0, b1) \
    asm volatile("mma.sync.aligned.m16n8k8.row.col.f32.tf32.tf32.f32 " \
        "{%0,%1,%2,%3}, {%4,%5,%6,%7}, {%8,%9}, {%0,%1,%2,%3};" \
        : "+f"((c)[0]), "+f"((c)[1]), "+f"((c)[2]), "+f"((c)[3]) \
        : "r"(a0), "r"(a1), "r"(a2), "r"(a3), "r"(b0), "r"(b1))

// ---------------- prepacks (tf32 fragment-linear) ----------------
__global__ void prepack_wf_kernel(const float* __restrict__ si0, const float* __restrict__ si1,
                                  const float* __restrict__ l10, const float* __restrict__ l11) {
    int idx = blockIdx.x * blockDim.x + threadIdx.x;
    if (idx >= 40 * 4 * 16 * 32) return;
    int lane = idx & 31;
    int nt = (idx >> 5) & 15;
    int kc = (idx >> 9) & 3;
    int s = idx >> 11;
    int ch = s / 10, v = s % 10;
    int gid = lane >> 2, t2 = lane & 3;
    int n = nt * 8 + gid;
    int w = n & 63;
    const float* src = (n >= 64) ? (ch == 0 ? l10 : l11) : (ch == 0 ? si0 : si1);
    int u0 = kc * 16 + t2;
    // chunk0: k = t2, t2+4 ; chunk1: k = t2+8, t2+12
    float b00 = src[((u0 + 0) * 10 + v) * 64 + w];
    float b10 = src[((u0 + 4) * 10 + v) * 64 + w];
    float b01 = src[((u0 + 8) * 10 + v) * 64 + w];
    float b11 = src[((u0 + 12) * 10 + v) * 64 + w];
    g_WF[idx] = make_uint4(tf32c(b00), tf32c(b10), tf32c(b01), tf32c(b11));
}

__global__ void prepack_wf2_kernel(const float* __restrict__ l20, const float* __restrict__ l21) {
    int idx = blockIdx.x * blockDim.x + threadIdx.x;
    if (idx >= 40 * 4 * 8 * 32) return;
    int lane = idx & 31;
    int nt = (idx >> 5) & 7;
    int kc = (idx >> 8) & 3;
    int s = idx >> 10;
    int ch = s / 10, v = s % 10;
    int gid = lane >> 2, t2 = lane & 3;
    int w = nt * 8 + gid;      // 0..63
    const float* src = (ch == 0) ? l20 : l21;
    int u0 = kc * 16 + t2;
    float b00 = src[((u0 + 0) * 10 + v) * 64 + w];
    float b10 = src[((u0 + 4) * 10 + v) * 64 + w];
    float b01 = src[((u0 + 8) * 10 + v) * 64 + w];
    float b11 = src[((u0 + 12) * 10 + v) * 64 + w];
    g_WF2[idx] = make_uint4(tf32c(b00), tf32c(b10), tf32c(b01), tf32c(b11));
}

__global__ void prepack_tp_kernel(const float* __restrict__ tpw) {
    int i = blockIdx.x * blockDim.x + threadIdx.x;
    if (i >= 32 * 32) return;
    int d = i >> 5, lane = i & 31;
    const float* row = tpw + d * 256;
    float* a = g_tppA + i * 4;
    a[0] = row[lane];        a[1] = row[64 + lane];
    a[2] = row[128 + lane];  a[3] = row[192 + lane];
    float* b = g_tppB + i * 4;
    b[0] = row[32 + lane];   b[1] = row[96 + lane];
    b[2] = row[160 + lane];  b[3] = row[224 + lane];
}

__global__ void zero_agg_kernel(int n4) {
    float4* p = (float4*)g_agg;
    float4 z = make_float4(0.f, 0.f, 0.f, 0.f);
    for (int i = blockIdx.x * blockDim.x + threadIdx.x; i < n4; i += gridDim.x * blockDim.x)
        p[i] = z;
}

// ---------------- fctp dual via tf32 mma.sync ----------------
#define OFF_XS 65536
#define OFF_ZS (65536 + 34816)
#define SMEM_NEED (65536 + 34816 + 5120)

__global__ __launch_bounds__(256, 2) void fctp_dual_mma_kernel(
    const float* __restrict__ x, const float* __restrict__ z,
    float* __restrict__ out_s, int nn)
{
    extern __shared__ char sm[];
    char* Bsm = sm;
    float* xs = (float*)(sm + OFF_XS);
    float* zs = (float*)(sm + OFF_ZS);

    const int t = threadIdx.x;
    const int wid = t >> 5;
    const int lane = t & 31;
    const int gid = lane >> 2;
    const int t2 = lane & 3;
    const int warp_m = wid & 3;
    const int warp_n = wid >> 2;
    const int nbase = blockIdx.x * 128;

    const uint32_t bsm_u = smem_u32(Bsm);

    for (int i = t; i < 1280; i += 256) {
        int node = nbase + i / 10;
        zs[i] = (node < nn) ? z[(size_t)nbase * 10 + i] : 0.f;
    }
    {
        const uint4* gsrc = g_WF;
#pragma unroll
        for (int k = 0; k < 8; k++)
            cp16(bsm_u + t * 16 + k * 4096, gsrc + t + k * 256);
        cp_commit();
    }

    float acc[2][8][4];
#pragma unroll
    for (int a = 0; a < 2; a++)
#pragma unroll
        for (int b = 0; b < 8; b++)
#pragma unroll
            for (int c = 0; c < 4; c++) acc[a][b][c] = 0.f;

    const float sc = 0.03952847075210474f;  // 1/sqrt(640)

    for (int s = 0; s < 40; s++) {
        const int ch = s / 10;
        const int v = s % 10;
        const int buf = s & 1;

        __syncthreads();

        if (v == 0) {
            for (int i = t; i < 8192; i += 256) {
                int row = i >> 6, u = i & 63;
                int node = nbase + row;
                int col = (ch == 0) ? u : (64 + 3 * u + (ch - 1));
                xs[row * 68 + u] = (node < nn) ? x[(size_t)node * 256 + col] : 0.f;
            }
        }
        if (s + 1 < 40) {
            const uint4* gsrc = g_WF + (size_t)(s + 1) * 2048;
            uint32_t dst = bsm_u + (buf ^ 1) * 32768;
#pragma unroll
            for (int k = 0; k < 8; k++)
                cp16(dst + t * 16 + k * 4096, gsrc + t + k * 256);
        }
        cp_commit();
        cp_waitg1();
        __syncthreads();

        float zr[2][2];
#pragma unroll
        for (int mt = 0; mt < 2; mt++) {
            int r = warp_m * 32 + mt * 16 + gid;
            zr[mt][0] = zs[r * 10 + v];
            zr[mt][1] = zs[(r + 8) * 10 + v];
        }

        char* Bbuf = Bsm + buf * 32768;

#pragma unroll 1
        for (int kc = 0; kc < 4; kc++) {
            uint32_t A0[2][4], A1[2][4];
#pragma unroll
            for (int mt = 0; mt < 2; mt++) {
                int r0 = warp_m * 32 + mt * 16 + gid;
                int ub = kc * 16 + t2;
                const float* xr0 = xs + r0 * 68;
                const float* xr1 = xs + (r0 + 8) * 68;
                float z0 = zr[mt][0], z1 = zr[mt][1];
                A0[mt][0] = tf32c(xr0[ub] * z0);
                A0[mt][1] = tf32c(xr1[ub] * z1);
                A0[mt][2] = tf32c(xr0[ub + 4] * z0);
                A0[mt][3] = tf32c(xr1[ub + 4] * z1);
                A1[mt][0] = tf32c(xr0[ub + 8] * z0);
                A1[mt][1] = tf32c(xr1[ub + 8] * z1);
                A1[mt][2] = tf32c(xr0[ub + 12] * z0);
                A1[mt][3] = tf32c(xr1[ub + 12] * z1);
            }
#pragma unroll
            for (int nt = 0; nt < 8; nt++) {
                uint4 B4 = *(const uint4*)(Bbuf + (((kc * 16) + warp_n * 8 + nt) * 32 + lane) * 16);
#pragma unroll
                for (int mt = 0; mt < 2; mt++) {
                    MMATF32(acc[mt][nt], A0[mt][0], A0[mt][1], A0[mt][2], A0[mt][3], B4.x, B4.y);
                    MMATF32(acc[mt][nt], A1[mt][0], A1[mt][1], A1[mt][2], A1[mt][3], B4.z, B4.w);
                }
            }
        }

        if (v == 9) {
#pragma unroll
            for (int mt = 0; mt < 2; mt++) {
#pragma unroll
                for (int nt = 0; nt < 8; nt++) {
                    int ntg = warp_n * 8 + nt;
                    int n0 = ntg * 8 + t2 * 2;
                    int r0 = nbase + warp_m * 32 + mt * 16 + gid;
                    int r1 = r0 + 8;
                    float c0 = acc[mt][nt][0] * sc;
                    float c1 = acc[mt][nt][1] * sc;
                    float c2 = acc[mt][nt][2] * sc;
                    float c3 = acc[mt][nt][3] * sc;
                    if (warp_n == 0) {
                        int w = n0;
                        if (ch == 0) {
                            if (r0 < nn) *(float2*)(out_s + (size_t)r0 * 256 + w) = make_float2(c0, c1);
                            if (r1 < nn) *(float2*)(out_s + (size_t)r1 * 256 + w) = make_float2(c2, c3);
                        } else {
                            int off = 64 + 3 * w + (ch - 1);
                            if (r0 < nn) {
                                out_s[(size_t)r0 * 256 + off] = c0;
                                out_s[(size_t)r0 * 256 + off + 3] = c1;
                            }
                            if (r1 < nn) {
                                out_s[(size_t)r1 * 256 + off] = c2;
                                out_s[(size_t)r1 * 256 + off + 3] = c3;
                            }
                        }
                    } else {
                        int w = n0 - 64;
                        float* xlp = g_xl + (size_t)ch * PLANE;
                        if (r0 < nn) *(float2*)(xlp + (size_t)r0 * 64 + w) = make_float2(c0, c1);
                        if (r1 < nn) *(float2*)(xlp + (size_t)r1 * 64 + w) = make_float2(c2, c3);
                    }
                    acc[mt][nt][0] = 0.f; acc[mt][nt][1] = 0.f;
                    acc[mt][nt][2] = 0.f; acc[mt][nt][3] = 0.f;
                }
            }
        }
    }
}

// ---------------- fctp final via tf32 mma.sync (N=64) ----------------
#define F_OFF_XS 32768
#define F_OFF_ZS (32768 + 34816)
#define F_SMEM_NEED (32768 + 34816 + 5120)

__global__ __launch_bounds__(256, 2) void fctp_final_mma_kernel(
    const float* __restrict__ z, float* __restrict__ out, int nn)
{
    extern __shared__ char sm[];
    char* Bsm = sm;
    float* xs = (float*)(sm + F_OFF_XS);
    float* zs = (float*)(sm + F_OFF_ZS);

    const int t = threadIdx.x;
    const int wid = t >> 5;
    const int lane = t & 31;
    const int gid = lane >> 2;
    const int t2 = lane & 3;
    const int nbase = blockIdx.x * 128;

    const uint32_t bsm_u = smem_u32(Bsm);

    for (int i = t; i < 1280; i += 256) {
        int node = nbase + i / 10;
        zs[i] = (node < nn) ? z[(size_t)nbase * 10 + i] : 0.f;
    }
    {
        const uint4* gsrc = g_WF2;
#pragma unroll
        for (int k = 0; k < 4; k++)
            cp16(bsm_u + t * 16 + k * 4096, gsrc + t + k * 256);
        cp_commit();
    }

    float acc[8][4];
#pragma unroll
    for (int b = 0; b < 8; b++)
#pragma unroll
        for (int c = 0; c < 4; c++) acc[b][c] = 0.f;

    const float sc = 0.03952847075210474f * 0.1f;
    const float4* agg4 = (const float4*)g_agg;

    for (int s = 0; s < 40; s++) {
        const int ch = s / 10;
        const int v = s % 10;
        const int buf = s & 1;

        __syncthreads();

        if (v == 0) {
            for (int i = t; i < 8192; i += 256) {
                int row = i >> 6, u = i & 63;
                int node = nbase + row;
                float val = 0.f;
                if (node < nn) {
                    float4 q = agg4[(size_t)node * 64 + u];
                    val = (ch == 0) ? q.x : (ch == 1) ? q.y : (ch == 2) ? q.z : q.w;
                }
                xs[row * 68 + u] = val;
            }
        }
        if (s + 1 < 40) {
            const uint4* gsrc = g_WF2 + (size_t)(s + 1) * 1024;
            uint32_t dst = bsm_u + (buf ^ 1) * 16384;
#pragma unroll
            for (int k = 0; k < 4; k++)
                cp16(dst + t * 16 + k * 4096, gsrc + t + k * 256);
        }
        cp_commit();
        cp_waitg1();
        __syncthreads();

        int r0g = wid * 16 + gid;
        float z0 = zs[r0g * 10 + v];
        float z1 = zs[(r0g + 8) * 10 + v];

        char* Bbuf = Bsm + buf * 16384;

#pragma unroll 1
        for (int kc = 0; kc < 4; kc++) {
            uint32_t A0[4], A1[4];
            {
                int ub = kc * 16 + t2;
                const float* xr0 = xs + r0g * 68;
                const float* xr1 = xs + (r0g + 8) * 68;
                A0[0] = tf32c(xr0[ub] * z0);
                A0[1] = tf32c(xr1[ub] * z1);
                A0[2] = tf32c(xr0[ub + 4] * z0);
                A0[3] = tf32c(xr1[ub + 4] * z1);
                A1[0] = tf32c(xr0[ub + 8] * z0);
                A1[1] = tf32c(xr1[ub + 8] * z1);
                A1[2] = tf32c(xr0[ub + 12] * z0);
                A1[3] = tf32c(xr1[ub + 12] * z1);
            }
#pragma unroll
            for (int nt = 0; nt < 8; nt++) {
                uint4 B4 = *(const uint4*)(Bbuf + ((kc * 8 + nt) * 32 + lane) * 16);
                MMATF32(acc[nt], A0[0], A0[1], A0[2], A0[3], B4.x, B4.y);
                MMATF32(acc[nt], A1[0], A1[1], A1[2], A1[3], B4.z, B4.w);
            }
        }

        if (v == 9) {
#pragma unroll
            for (int nt = 0; nt < 8; nt++) {
                int w = nt * 8 + t2 * 2;
                int r0 = nbase + wid * 16 + gid;
                int r1 = r0 + 8;
                float c0 = acc[nt][0] * sc;
                float c1 = acc[nt][1] * sc;
                float c2 = acc[nt][2] * sc;
                float c3 = acc[nt][3] * sc;
                if (ch == 0) {
                    if (r0 < nn) {
                        float2* p = (float2*)(out + (size_t)r0 * 256 + w);
                        float2 o = *p; o.x += c0; o.y += c1; *p = o;
                    }
                    if (r1 < nn) {
                        float2* p = (float2*)(out + (size_t)r1 * 256 + w);
                        float2 o = *p; o.x += c2; o.y += c3; *p = o;
                    }
                } else {
                    int off = 64 + 3 * w + (ch - 1);
                    if (r0 < nn) {
                        out[(size_t)r0 * 256 + off] += c0;
                        out[(size_t)r0 * 256 + off + 3] += c1;
                    }
                    if (r1 < nn) {
                        out[(size_t)r1 * 256 + off] += c2;
                        out[(size_t)r1 * 256 + off + 3] += c3;
                    }
                }
                acc[nt][0] = 0.f; acc[nt][1] = 0.f;
                acc[nt][2] = 0.f; acc[nt][3] = 0.f;
            }
        }
    }
}

// ---------------- edge kernel: 4 edges/warp, gathers issued before GEMM ----------------
#define EPW 4
__global__ __launch_bounds__(256) void edge_kernel(
    const int* __restrict__ esrc, const int* __restrict__ edst,
    const float* __restrict__ elen, const float* __restrict__ eattr,
    int n_edges)
{
    const int warp = threadIdx.x >> 5;
    const int lane = threadIdx.x & 31;
    const int ebase = (blockIdx.x * 8 + warp) * EPW;
    if (ebase >= n_edges) return;

    float el[EPW];
    int esafe[EPW];
    bool valid[EPW];
#pragma unroll
    for (int j = 0; j < EPW; j++) {
        int e = ebase + j;
        valid[j] = (e < n_edges);
        esafe[j] = valid[j] ? e : (n_edges - 1);
        el[j] = elen[(size_t)esafe[j] * 32 + lane];
    }

    // Issue ALL gathers before the GEMM so their latency is covered by compute.
    float gx[EPW][8];
#pragma unroll
    for (int j = 0; j < EPW; j++) {
        const float* xb = g_xl + (size_t)esrc[esafe[j]] * 64;
#pragma unroll
        for (int h = 0; h < 2; h++) {
            int u = lane + 32 * h;
            gx[j][h * 4 + 0] = xb[u];
            gx[j][h * 4 + 1] = xb[1 * PLANE + u];
            gx[j][h * 4 + 2] = xb[2 * PLANE + u];
            gx[j][h * 4 + 3] = xb[3 * PLANE + u];
        }
    }

    u64t acc2[EPW * 4];
#pragma unroll
    for (int i = 0; i < EPW * 4; i++) acc2[i] = 0ull;
    const ulonglong2* tpA8 = (const ulonglong2*)g_tppA;
    const ulonglong2* tpB8 = (const ulonglong2*)g_tppB;
#pragma unroll 8
    for (int d = 0; d < 32; d++) {
        ulonglong2 tA = tpA8[d * 32 + lane];
        ulonglong2 tB = tpB8[d * 32 + lane];
#pragma unroll
        for (int j = 0; j < EPW; j++) {
            u64t ed = pack2s(__shfl_sync(0xffffffffu, el[j], d));
            ffma2(acc2[j * 4 + 0], ed, tA.x);
            ffma2(acc2[j * 4 + 1], ed, tA.y);
            ffma2(acc2[j * 4 + 2], ed, tB.x);
            ffma2(acc2[j * 4 + 3], ed, tB.y);
        }
    }

    const float ISQ2 = 0.7071067811865476f;
    const float ISQ3 = 0.5773502691896258f;

#pragma unroll
    for (int j = 0; j < EPW; j++) {
        if (!valid[j]) continue;
        int e = esafe[j];
        int dst = edst[e];
        float4 at = ((const float4*)eattr)[e];

        float wv[8];
        unpack2(acc2[j * 4 + 0], wv[0], wv[1]);
        unpack2(acc2[j * 4 + 1], wv[2], wv[3]);
        unpack2(acc2[j * 4 + 2], wv[4], wv[5]);
        unpack2(acc2[j * 4 + 3], wv[6], wv[7]);

        float* aggp = g_agg + (size_t)dst * FEAT;
#pragma unroll
        for (int h = 0; h < 2; h++) {
            int u = lane + 32 * h;
            float x0  = gx[j][h * 4 + 0];
            float x10 = gx[j][h * 4 + 1];
            float x11 = gx[j][h * 4 + 2];
            float x12 = gx[j][h * 4 + 3];
            float w1  = wv[h * 4 + 0];
            float w2v = wv[h * 4 + 1];
            float w3  = wv[h * 4 + 2];
            float w4v = wv[h * 4 + 3];
            float dot = x10 * at.y + x11 * at.z + x12 * at.w;
            float4 o;
            o.x = ISQ2 * (w1 * x0 * at.x + ISQ3 * w4v * dot);
            o.y = ISQ2 * (w2v * x0 * at.y + w3 * x10 * at.x);
            o.z = ISQ2 * (w2v * x0 * at.z + w3 * x11 * at.x);
            o.w = ISQ2 * (w2v * x0 * at.w + w3 * x12 * at.x);
            red_add_v4(aggp + u * 4, o);
        }
    }
}

// ---------------- launch ----------------
extern "C" void kernel_launch(void* const* d_in, const int* in_sizes, int n_in,
                              void* d_out, int out_size) {
    const float* x     = (const float*)d_in[0];
    const float* z     = (const float*)d_in[1];
    const int*   esrc  = (const int*)d_in[2];
    const int*   edst  = (const int*)d_in[3];
    const float* elen  = (const float*)d_in[4];
    const float* eattr = (const float*)d_in[5];
    const float* Wsi0  = (const float*)d_in[6];
    const float* Wsi1  = (const float*)d_in[7];
    const float* Wl10  = (const float*)d_in[8];
    const float* Wl11  = (const float*)d_in[9];
    const float* Wl20  = (const float*)d_in[10];
    const float* Wl21  = (const float*)d_in[11];
    const float* tpw   = (const float*)d_in[12];
    float* out = (float*)d_out;

    const int n_nodes = in_sizes[0] / FEAT;
    const int n_edges = in_sizes[2];

    cudaFuncSetAttribute(fctp_dual_mma_kernel,
                         cudaFuncAttributeMaxDynamicSharedMemorySize, SMEM_NEED);
    cudaFuncSetAttribute(fctp_final_mma_kernel,
                         cudaFuncAttributeMaxDynamicSharedMemorySize, F_SMEM_NEED);

    prepack_wf_kernel<<<(40 * 4 * 16 * 32 + 255) / 256, 256>>>(Wsi0, Wsi1, Wl10, Wl11);
    prepack_wf2_kernel<<<(40 * 4 * 8 * 32 + 255) / 256, 256>>>(Wl20, Wl21);
    prepack_tp_kernel<<<4, 256>>>(tpw);
    zero_agg_kernel<<<512, 256>>>(n_nodes * (FEAT / 4));

    const int ntiles = (n_nodes + 127) / 128;
    fctp_dual_mma_kernel<<<ntiles, 256, SMEM_NEED>>>(x, z, out, n_nodes);

    const int edges_per_block = 8 * EPW;
    edge_kernel<<<(n_edges + edges_per_block - 1) / edges_per_block, 256>>>(
        esrc, edst, elen, eattr, n_edges);

    fctp_final_mma_kernel<<<ntiles, 256, F_SMEM_NEED>>>(z, out, n_nodes);
}